// round 16
// baseline (speedup 1.0000x reference)
#include <cuda_runtime.h>
#include <math.h>
#include <stdint.h>

#define N_ITEMS 200000
#define N_USERS 100000
#define N_INTER 2000000
#define GCN 64
#define HID 256
#define TOW 128

typedef unsigned long long u64;

// packed dual-FMA: (d.lo,d.hi) += (a.lo*b.lo, a.hi*b.hi)
#define FMA2(d, a, b) \
    asm("fma.rn.f32x2 %0, %1, %2, %0;" : "+l"(d) : "l"(a), "l"(b))

#define UNPACK2(lo, hi, p) \
    asm("mov.b64 {%0, %1}, %2;" : "=f"(lo), "=f"(hi) : "l"(p))

__device__ __forceinline__ uint32_t smem_u32(const void* p) {
    uint32_t a;
    asm("{ .reg .u64 t; cvta.to.shared.u64 t, %1; cvt.u32.u64 %0, t; }"
        : "=r"(a) : "l"(p));
    return a;
}

// cp.async 16B with runtime src-size (0 -> zero-fill)
#define CP_ASYNC16(dst_u32, src_ptr, nbytes) \
    asm volatile("cp.async.cg.shared.global [%0], [%1], 16, %2;" \
                 :: "r"(dst_u32), "l"(src_ptr), "r"(nbytes))
#define CP_COMMIT() asm volatile("cp.async.commit_group;" ::: "memory")
template <int NPend>
__device__ __forceinline__ void cp_wait() {
    asm volatile("cp.async.wait_group %0;" :: "n"(NPend) : "memory");
}

// ---------------- scratch (static device globals; no runtime alloc) ----------
__device__ float g_item_emb[(size_t)N_ITEMS * TOW];      // 102.4 MB
__device__ float g_H[(size_t)N_ITEMS * HID];             // 204.8 MB
__device__ float g_fused[(size_t)N_USERS * (GCN + TOW)]; // 76.8 MB
__device__ int   g_start[N_USERS];
__device__ int   g_end[N_USERS];

// W row stride: multiple of 4 words AND ≡4 (mod 8) -> distinct-lane LDS.128
// over W rows is bank-conflict-free. X needs NO pad: its loads are broadcasts.
template <int K> struct PadK {
    static constexpr int a = (K + 3) & ~3;
    static constexpr int value = (a % 8 == 4) ? a : a + 4;
};

// ---------------------------------------------------------------------------
// Fused layer: Y = post( X @ W + b )   [512 threads, persistent CTAs]
//  - ONE barrier per chunk: order is  cp_wait(all) -> sync -> prefetch-next
//    -> compute.  The single barrier both publishes the current chunk and
//    retires all reads of the buffer about to be refilled (those reads
//    happened in the previous chunk's compute, before this barrier).
//  - Cross-tile chunk stream: the prefetch during a tile's LAST chunk is the
//    NEXT tile's chunk 0, so the epilogue + tile turn overlap staging.
//    (SPLIT is even, so chunk 0 always lands in buffer 0.)
//  - PDL: W staging (inputs only) runs before cudaGridDependencySynchronize.
// ---------------------------------------------------------------------------
template <int K, int N, int LANES, int R, int SPLIT, bool RELU, bool L2N, bool CONCAT>
__global__ void __launch_bounds__(512, 1)
gemm_kernel(const float* __restrict__ X1, int k1,
            const float* __restrict__ X2,
            const float* __restrict__ W,
            const float* __restrict__ bias,
            float* __restrict__ Y, int M)
{
    constexpr int THREADS = 512;
    constexpr int KC  = K / SPLIT;                       // chunk K width
    constexpr int XS  = CONCAT ? PadK<KC>::value : KC;   // X row stride
    constexpr int K4w = PadK<K>::value;                  // W row stride
    constexpr int C   = 4;
    constexpr int G   = THREADS / LANES;
    constexpr int TR  = G * R;
    constexpr int NG  = XS / 4;                          // 4-k groups per chunk
    constexpr int NBUF = (SPLIT > 1) ? 2 : 1;

    static_assert(N == LANES * C, "4 cols per thread");
    static_assert(K % SPLIT == 0, "even K split");
    static_assert(CONCAT || (KC % 4 == 0 && SPLIT % 2 == 0), "stream parity");
    static_assert(!L2N || (N == 128 && LANES == 32), "L2N: warp-local rows");
    static_assert(!CONCAT || SPLIT == 1, "concat layer is single-chunk");

    cudaTriggerProgrammaticLaunchCompletion();

    extern __shared__ float sm[];
    float* Ws = sm;                          // [N][K4w]
    float* Xb[NBUF];
    Xb[0] = sm + (size_t)N * K4w;
    if (NBUF == 2) Xb[1] = Xb[0] + (size_t)TR * XS;

    const int tid = threadIdx.x;
    const int ty  = tid / LANES;
    const int tx  = tid % LANES;

    // ---- stage transposed weights (inputs only -> runs pre-sync) ----
    for (int i = tid; i < K * N; i += THREADS) {
        int k = i / N, n = i - k * N;
        Ws[n * K4w + k] = W[i];
    }
    for (int i = tid; i < N * (K4w - K); i += THREADS) {
        int n = i / (K4w - K), k = K + (i - n * (K4w - K));
        Ws[n * K4w + k] = 0.f;
    }
    // ---- zero X pads once (CONCAT only; staging never writes words KC..XS) --
    if (XS > KC) {
        for (int i = tid; i < TR; i += THREADS)
#pragma unroll
            for (int p = KC; p < XS; ++p) Xb[0][i * XS + p] = 0.f;
    }

    float breg[C];
#pragma unroll
    for (int j = 0; j < C; ++j) breg[j] = bias[tx + LANES * j];

    // predecessor's output (X) becomes valid after this
    cudaGridDependencySynchronize();

    const ulonglong2* wb = reinterpret_cast<const ulonglong2*>(Ws + (size_t)tx * K4w);
    const ulonglong2* xbp[NBUF];
#pragma unroll
    for (int b = 0; b < NBUF; ++b)
        xbp[b] = reinterpret_cast<const ulonglong2*>(Xb[b] + (size_t)ty * XS);
    constexpr int WSTEP = LANES * K4w / 4;
    constexpr int XSTEP = G * XS / 4;

    const float4* X4 = reinterpret_cast<const float4*>(X1);
    constexpr int KV = (KC + 3) / 4;         // float4 per row per chunk

    const int ntiles = (M + TR - 1) / TR;

    if (!CONCAT) {
        // staging helper: chunk (t, c) -> buffer pb
        auto stage = [&](int t, int c, int pb) {
            const int r0 = t * TR;
            for (int i = tid; i < TR * KV; i += THREADS) {
                int r = i / KV, c4 = i - r * KV;
                int gr = r0 + r;
                uint32_t dst = smem_u32(Xb[pb] + r * XS + 4 * c4);
                const float4* src = X4 + (size_t)(gr < M ? gr : 0) * (K / 4)
                                  + c * KV + c4;
                CP_ASYNC16(dst, src, (gr < M) ? 16 : 0);
            }
            CP_COMMIT();
        };

        if (blockIdx.x < ntiles) stage(blockIdx.x, 0, 0);   // cold start

        for (int tile = blockIdx.x; tile < ntiles; tile += gridDim.x) {
            const int row0 = tile * TR;

            u64 acc[R][C];
#pragma unroll
            for (int i = 0; i < R; ++i)
#pragma unroll
                for (int j = 0; j < C; ++j) acc[i][j] = 0ull;

#pragma unroll 1
            for (int cch = 0; cch < SPLIT; ++cch) {
                cp_wait<0>();       // current chunk landed (my groups drained)
                __syncthreads();    // publish current; retire reads of other buf

                // prefetch the NEXT chunk in the stream (possibly next tile's 0)
                if (cch + 1 < SPLIT)
                    stage(tile, cch + 1, (cch + 1) & 1);
                else if (tile + (int)gridDim.x < ntiles)
                    stage(tile + gridDim.x, 0, 0);

                const ulonglong2* xb = xbp[cch & 1];
                const int goff = cch * (KC / 4);
#pragma unroll 2
                for (int g = 0; g < NG; ++g) {
                    ulonglong2 w[C];
#pragma unroll
                    for (int j = 0; j < C; ++j) w[j] = wb[goff + g + j * WSTEP];
#pragma unroll
                    for (int i = 0; i < R; ++i) {
                        ulonglong2 a = xb[g + i * XSTEP];   // warp-broadcast
#pragma unroll
                        for (int j = 0; j < C; ++j) {
                            FMA2(acc[i][j], a.x, w[j].x);
                            FMA2(acc[i][j], a.y, w[j].y);
                        }
                    }
                }
            }

            // ---- epilogue (registers + shfl only; next prefetch in flight) --
            float val[R][C];
#pragma unroll
            for (int i = 0; i < R; ++i)
#pragma unroll
                for (int j = 0; j < C; ++j) {
                    float lo, hi;
                    UNPACK2(lo, hi, acc[i][j]);
                    val[i][j] = lo + hi + breg[j];
                }

            if (RELU) {
#pragma unroll
                for (int i = 0; i < R; ++i) {
                    int gr = row0 + ty + G * i;
                    if (gr < M) {
#pragma unroll
                        for (int j = 0; j < C; ++j)
                            Y[(size_t)gr * N + tx + LANES * j] = fmaxf(val[i][j], 0.f);
                    }
                }
            } else {   // L2N: each row lives in one warp
#pragma unroll
                for (int i = 0; i < R; ++i) {
                    float s = val[i][0] * val[i][0] + val[i][1] * val[i][1]
                            + val[i][2] * val[i][2] + val[i][3] * val[i][3];
#pragma unroll
                    for (int o = 16; o > 0; o >>= 1)
                        s += __shfl_xor_sync(0xffffffffu, s, o);
                    float scale = 1.0f / fmaxf(sqrtf(s), 1e-12f);
                    int gr = row0 + ty + G * i;
                    if (gr < M) {
#pragma unroll
                        for (int j = 0; j < C; ++j)
                            Y[(size_t)gr * 128 + tx + 32 * j] = val[i][j] * scale;
                    }
                }
            }
        }
        return;
    }

    // ---------------- CONCAT path (SPLIT==1, direct stores) ----------------
    for (int tile = blockIdx.x; tile < ntiles; tile += gridDim.x) {
        const int row0 = tile * TR;
        __syncthreads();   // Xb[0] free (prev tile computed), W staged

        const float4* G4 = reinterpret_cast<const float4*>(X2);
        for (int u = tid; u < TR * 17; u += THREADS) {
            int r = u / 17, q = u - r * 17;
            int gr = row0 + r;
            if (q == 16) {
                float a0 = 0.f, a1 = 0.f;
                if (gr < M) { a0 = X1[gr * 2]; a1 = X1[gr * 2 + 1]; }
                Xb[0][r * XS + 0] = a0;
                Xb[0][r * XS + 1] = a1;
            } else {
                float4 v = make_float4(0.f, 0.f, 0.f, 0.f);
                if (gr < M) v = G4[(size_t)gr * 16 + q];
                int c0 = 2 + 4 * q;
                Xb[0][r * XS + c0]     = v.x;
                Xb[0][r * XS + c0 + 1] = v.y;
                Xb[0][r * XS + c0 + 2] = v.z;
                Xb[0][r * XS + c0 + 3] = v.w;
            }
        }
        __syncthreads();

        u64 acc[R][C];
#pragma unroll
        for (int i = 0; i < R; ++i)
#pragma unroll
            for (int j = 0; j < C; ++j) acc[i][j] = 0ull;

        const ulonglong2* xb = xbp[0];
#pragma unroll 1
        for (int g = 0; g < NG; ++g) {
            ulonglong2 w[C];
#pragma unroll
            for (int j = 0; j < C; ++j) w[j] = wb[g + j * WSTEP];
#pragma unroll
            for (int i = 0; i < R; ++i) {
                ulonglong2 a = xb[g + i * XSTEP];
#pragma unroll
                for (int j = 0; j < C; ++j) {
                    FMA2(acc[i][j], a.x, w[j].x);
                    FMA2(acc[i][j], a.y, w[j].y);
                }
            }
        }

        float val[R][C];
#pragma unroll
        for (int i = 0; i < R; ++i)
#pragma unroll
            for (int j = 0; j < C; ++j) {
                float lo, hi;
                UNPACK2(lo, hi, acc[i][j]);
                val[i][j] = lo + hi + breg[j];
            }

#pragma unroll
        for (int i = 0; i < R; ++i) {
            int gr = row0 + ty + G * i;
            if (gr < M) {
#pragma unroll
                for (int j = 0; j < C; ++j)
                    Y[(size_t)gr * N + tx + LANES * j] = fmaxf(val[i][j], 0.f);
            }
        }
    }
}

// ---------------------------------------------------------------------------
// Segment boundaries from sorted seg_ids (users with no interactions -> [0,0))
// ---------------------------------------------------------------------------
__global__ void bounds_init_kernel(int* __restrict__ s, int* __restrict__ e, int n)
{
    cudaTriggerProgrammaticLaunchCompletion();
    int i = blockIdx.x * blockDim.x + threadIdx.x;
    if (i < n) { s[i] = 0; e[i] = 0; }
}

__global__ void bounds_kernel(const int* __restrict__ seg, int n,
                              int* __restrict__ s, int* __restrict__ e)
{
    cudaTriggerProgrammaticLaunchCompletion();
    cudaGridDependencySynchronize();   // init's zeros must land first
    int i = blockIdx.x * blockDim.x + threadIdx.x;
    if (i >= n) return;
    int id = seg[i];
    if (i == 0 || seg[i - 1] != id) s[id] = i;
    if (i == n - 1 || seg[i + 1] != id) e[id] = i + 1;
}

// ---------------------------------------------------------------------------
// One warp per user: fused[u] = concat(gcn_user_emb[users[u]], mean(item_emb))
// ---------------------------------------------------------------------------
__global__ void hist_kernel(const float* __restrict__ item_emb,
                            const int* __restrict__ item_idx,
                            const int* __restrict__ sa,
                            const int* __restrict__ ea,
                            const float* __restrict__ gue,
                            const int* __restrict__ users,
                            float* __restrict__ fused, int n_users)
{
    cudaTriggerProgrammaticLaunchCompletion();
    int w = (blockIdx.x * blockDim.x + threadIdx.x) >> 5;
    int lane = threadIdx.x & 31;
    if (w >= n_users) return;

    int uu = users[w];

    if (lane < 16) {   // inputs only -> pre-sync
        float4 g = reinterpret_cast<const float4*>(gue + (size_t)uu * GCN)[lane];
        reinterpret_cast<float4*>(fused + (size_t)w * (GCN + TOW))[lane] = g;
    }

    cudaGridDependencySynchronize();   // item_emb + sa/ea valid from here

    int s = sa[uu], e = ea[uu];
    const float4* emb4 = reinterpret_cast<const float4*>(item_emb);

    float4 acc = make_float4(0.f, 0.f, 0.f, 0.f);
    int j = s;
    for (; j + 4 <= e; j += 4) {
        int i0 = item_idx[j], i1 = item_idx[j + 1], i2 = item_idx[j + 2], i3 = item_idx[j + 3];
        float4 v0 = emb4[(size_t)i0 * 32 + lane];
        float4 v1 = emb4[(size_t)i1 * 32 + lane];
        float4 v2 = emb4[(size_t)i2 * 32 + lane];
        float4 v3 = emb4[(size_t)i3 * 32 + lane];
        acc.x += (v0.x + v1.x) + (v2.x + v3.x);
        acc.y += (v0.y + v1.y) + (v2.y + v3.y);
        acc.z += (v0.z + v1.z) + (v2.z + v3.z);
        acc.w += (v0.w + v1.w) + (v2.w + v3.w);
    }
    for (; j < e; ++j) {
        int it = item_idx[j];
        float4 v = emb4[(size_t)it * 32 + lane];
        acc.x += v.x; acc.y += v.y; acc.z += v.z; acc.w += v.w;
    }
    float inv = 1.0f / fmaxf((float)(e - s), 1.0f);
    float4 m = make_float4(acc.x * inv, acc.y * inv, acc.z * inv, acc.w * inv);
    reinterpret_cast<float4*>(fused + (size_t)w * (GCN + TOW) + GCN)[lane] = m;
}

// ---------------------------------------------------------------------------
extern "C" void kernel_launch(void* const* d_in, const int* in_sizes, int n_in,
                              void* d_out, int out_size)
{
    const float* item_feat    = (const float*)d_in[0];
    const float* gcn_item_emb = (const float*)d_in[1];
    const float* gcn_user_emb = (const float*)d_in[2];
    const float* Wi1 = (const float*)d_in[3];
    const float* bi1 = (const float*)d_in[4];
    const float* Wi2 = (const float*)d_in[5];
    const float* bi2 = (const float*)d_in[6];
    const float* Wu1 = (const float*)d_in[7];
    const float* bu1 = (const float*)d_in[8];
    const float* Wu2 = (const float*)d_in[9];
    const float* bu2 = (const float*)d_in[10];
    const int* item_idx = (const int*)d_in[11];
    const int* seg_ids  = (const int*)d_in[12];
    const int* users    = (const int*)d_in[13];
    float* out = (float*)d_out;

    float *item_emb, *H, *fused;
    int *st, *en;
    cudaGetSymbolAddress((void**)&item_emb, g_item_emb);
    cudaGetSymbolAddress((void**)&H, g_H);
    cudaGetSymbolAddress((void**)&fused, g_fused);
    cudaGetSymbolAddress((void**)&st, g_start);
    cudaGetSymbolAddress((void**)&en, g_end);

    // instantiations (512 threads):
    //  i1: K=66  N=256 LANES=64 R=8 SPLIT=1 CONCAT  TR=64
    //  l2: K=256 N=128 LANES=32 R=6 SPLIT=4 L2N     TR=96  (both towers)
    //  u1: K=192 N=256 LANES=64 R=6 SPLIT=4 RELU    TR=48
    const int smem_i1 = (256 * PadK<66>::value  + 1 * 64 * PadK<66>::value) * 4; //  87,040
    const int smem_l2 = (128 * PadK<256>::value + 2 * 96 * 64) * 4;              // 182,272
    const int smem_u1 = (256 * PadK<192>::value + 2 * 48 * 48) * 4;              // 219,136

    cudaFuncSetAttribute((const void*)gemm_kernel<66, 256, 64, 8, 1, true, false, true>,
                         cudaFuncAttributeMaxDynamicSharedMemorySize, smem_i1);
    cudaFuncSetAttribute((const void*)gemm_kernel<256, 128, 32, 6, 4, false, true, false>,
                         cudaFuncAttributeMaxDynamicSharedMemorySize, smem_l2);
    cudaFuncSetAttribute((const void*)gemm_kernel<192, 256, 64, 6, 4, true, false, false>,
                         cudaFuncAttributeMaxDynamicSharedMemorySize, smem_u1);

    const int GRID = 152;   // persistent, 1 CTA per SM

    // PDL launch plumbing
    cudaLaunchAttribute pdl_attr[1];
    pdl_attr[0].id = cudaLaunchAttributeProgrammaticStreamSerialization;
    pdl_attr[0].val.programmaticStreamSerializationAllowed = 1;
    auto mkcfg = [&](unsigned gx, unsigned bx, size_t smem) {
        cudaLaunchConfig_t c;
        c.gridDim = dim3(gx, 1, 1);
        c.blockDim = dim3(bx, 1, 1);
        c.dynamicSmemBytes = smem;
        c.stream = 0;
        c.attrs = pdl_attr;
        c.numAttrs = 1;
        return c;
    };

    // 0) bounds init (first in chain; plain launch)
    bounds_init_kernel<<<(N_USERS + 255) / 256, 256>>>(st, en, N_USERS);

    // 1) bounds (syncs on init before writing)
    {
        cudaLaunchConfig_t c = mkcfg((N_INTER + 255) / 256, 256, 0);
        cudaLaunchKernelEx(&c, bounds_kernel, seg_ids, (int)N_INTER, st, en);
    }

    // 2) item L1: H = relu(concat(item_feat, gcn_item_emb) @ Wi1 + bi1)
    {
        cudaLaunchConfig_t c = mkcfg(GRID, 512, smem_i1);
        cudaLaunchKernelEx(&c, gemm_kernel<66, 256, 64, 8, 1, true, false, true>,
                           item_feat, 2, gcn_item_emb, Wi1, bi1, H, (int)N_ITEMS);
    }

    // 3) item L2 + L2 norm -> item_emb
    {
        cudaLaunchConfig_t c = mkcfg(GRID, 512, smem_l2);
        cudaLaunchKernelEx(&c, gemm_kernel<256, 128, 32, 6, 4, false, true, false>,
                           (const float*)H, 256, (const float*)H, Wi2, bi2,
                           item_emb, (int)N_ITEMS);
    }

    // 4) ragged gather + mean -> fused (gue copy pre-sync, gather post-sync)
    {
        cudaLaunchConfig_t c = mkcfg((N_USERS * 32 + 255) / 256, 256, 0);
        cudaLaunchKernelEx(&c, hist_kernel,
                           (const float*)item_emb, item_idx,
                           (const int*)st, (const int*)en,
                           gcn_user_emb, users, fused, (int)N_USERS);
    }

    // 5) user L1
    {
        cudaLaunchConfig_t c = mkcfg(GRID, 512, smem_u1);
        cudaLaunchKernelEx(&c, gemm_kernel<192, 256, 64, 6, 4, true, false, false>,
                           (const float*)fused, 192, (const float*)fused, Wu1, bu1,
                           H, (int)N_USERS);
    }

    // 6) user L2 + L2 norm -> output
    {
        cudaLaunchConfig_t c = mkcfg(GRID, 512, smem_l2);
        cudaLaunchKernelEx(&c, gemm_kernel<256, 128, 32, 6, 4, false, true, false>,
                           (const float*)H, 256, (const float*)H, Wu2, bu2,
                           out, (int)N_USERS);
    }
}

// round 17
// speedup vs baseline: 1.1772x; 1.1772x over previous
#include <cuda_runtime.h>
#include <math.h>
#include <stdint.h>

#define N_ITEMS 200000
#define N_USERS 100000
#define N_INTER 2000000
#define GCN 64
#define HID 256
#define TOW 128

typedef unsigned long long u64;

// packed dual-FMA: (d.lo,d.hi) += (a.lo*b.lo, a.hi*b.hi)
#define FMA2(d, a, b) \
    asm("fma.rn.f32x2 %0, %1, %2, %0;" : "+l"(d) : "l"(a), "l"(b))

#define UNPACK2(lo, hi, p) \
    asm("mov.b64 {%0, %1}, %2;" : "=f"(lo), "=f"(hi) : "l"(p))

__device__ __forceinline__ uint32_t smem_u32(const void* p) {
    uint32_t a;
    asm("{ .reg .u64 t; cvta.to.shared.u64 t, %1; cvt.u32.u64 %0, t; }"
        : "=r"(a) : "l"(p));
    return a;
}

// cp.async 16B with runtime src-size (0 -> zero-fill)
#define CP_ASYNC16(dst_u32, src_ptr, nbytes) \
    asm volatile("cp.async.cg.shared.global [%0], [%1], 16, %2;" \
                 :: "r"(dst_u32), "l"(src_ptr), "r"(nbytes))
#define CP_COMMIT() asm volatile("cp.async.commit_group;" ::: "memory")
template <int NPend>
__device__ __forceinline__ void cp_wait() {
    asm volatile("cp.async.wait_group %0;" :: "n"(NPend) : "memory");
}

// ---------------- scratch (static device globals; no runtime alloc) ----------
__device__ float g_item_emb[(size_t)N_ITEMS * TOW];      // 102.4 MB
__device__ float g_H[(size_t)N_ITEMS * HID];             // 204.8 MB
__device__ float g_fused[(size_t)N_USERS * (GCN + TOW)]; // 76.8 MB
__device__ int   g_start[N_USERS];
__device__ int   g_end[N_USERS];

// W row stride: multiple of 4 words AND ≡4 (mod 8) -> distinct-lane LDS.128
// over W rows is bank-conflict-free. X needs NO pad: its loads are broadcasts.
template <int K> struct PadK {
    static constexpr int a = (K + 3) & ~3;
    static constexpr int value = (a % 8 == 4) ? a : a + 4;
};

// ---------------------------------------------------------------------------
// Fused layer: Y = post( X @ W + b )   [512 threads, persistent CTAs]
//  - R14-validated pipeline: stage -> cp_wait<1> -> sync -> compute -> sync.
//  - CONCAT (i1): columns permuted to [gcn | feat] so the 64 gcn floats are
//    16B-aligned cp.async copies; W rows remapped identically (GEMM invariant
//    under consistent column/row permutation).
//  - PDL: W staging (inputs only) runs before cudaGridDependencySynchronize.
// ---------------------------------------------------------------------------
template <int K, int N, int LANES, int R, int SPLIT, bool RELU, bool L2N, bool CONCAT>
__global__ void __launch_bounds__(512, 1)
gemm_kernel(const float* __restrict__ X1, int k1,
            const float* __restrict__ X2,
            const float* __restrict__ W,
            const float* __restrict__ bias,
            float* __restrict__ Y, int M)
{
    constexpr int THREADS = 512;
    constexpr int KC  = K / SPLIT;                       // chunk K width
    constexpr int XS  = CONCAT ? PadK<KC>::value : KC;   // X row stride
    constexpr int K4w = PadK<K>::value;                  // W row stride
    constexpr int C   = 4;
    constexpr int G   = THREADS / LANES;
    constexpr int TR  = G * R;
    constexpr int NG  = XS / 4;                          // 4-k groups per chunk
    constexpr int NBUF = (SPLIT > 1) ? 2 : 1;

    static_assert(N == LANES * C, "4 cols per thread");
    static_assert(K % SPLIT == 0, "even K split");
    static_assert(CONCAT || KC % 4 == 0, "chunk multiple of 4");
    static_assert(!L2N || (N == 128 && LANES == 32), "L2N: warp-local rows");
    static_assert(!CONCAT || SPLIT == 1, "concat layer is single-chunk");

    cudaTriggerProgrammaticLaunchCompletion();

    extern __shared__ float sm[];
    float* Ws = sm;                          // [N][K4w]
    float* Xb[NBUF];
    Xb[0] = sm + (size_t)N * K4w;
    if (NBUF == 2) Xb[1] = Xb[0] + (size_t)TR * XS;

    const int tid = threadIdx.x;
    const int ty  = tid / LANES;
    const int tx  = tid % LANES;

    // ---- stage transposed weights (inputs only -> runs pre-sync) ----
    // CONCAT: remap k -> [gcn rows 0..63 | feat rows 64..65] to match the
    // permuted X layout below.
    for (int i = tid; i < K * N; i += THREADS) {
        int k = i / N, n = i - k * N;
        int kp = CONCAT ? ((k < 2) ? (K - 2 + k) : (k - 2)) : k;
        Ws[n * K4w + kp] = W[i];
    }
    for (int i = tid; i < N * (K4w - K); i += THREADS) {
        int n = i / (K4w - K), k = K + (i - n * (K4w - K));
        Ws[n * K4w + k] = 0.f;
    }
    // ---- zero X pads once (CONCAT only; staging never writes words KC..XS) --
    if (XS > KC) {
        for (int i = tid; i < TR; i += THREADS)
#pragma unroll
            for (int p = KC; p < XS; ++p) Xb[0][i * XS + p] = 0.f;
    }

    float breg[C];
#pragma unroll
    for (int j = 0; j < C; ++j) breg[j] = bias[tx + LANES * j];

    // predecessor's output (X) becomes valid after this
    cudaGridDependencySynchronize();

    const ulonglong2* wb = reinterpret_cast<const ulonglong2*>(Ws + (size_t)tx * K4w);
    const ulonglong2* xbp[NBUF];
#pragma unroll
    for (int b = 0; b < NBUF; ++b)
        xbp[b] = reinterpret_cast<const ulonglong2*>(Xb[b] + (size_t)ty * XS);
    constexpr int WSTEP = LANES * K4w / 4;
    constexpr int XSTEP = G * XS / 4;

    const float4* X4 = reinterpret_cast<const float4*>(X1);
    constexpr int KV = (KC + 3) / 4;         // float4 per row per chunk

    const int ntiles = (M + TR - 1) / TR;
    for (int tile = blockIdx.x; tile < ntiles; tile += gridDim.x) {
        const int row0 = tile * TR;
        __syncthreads();   // bufs free (prev tile fully computed), W staged

        // ---- stage chunk 0 ----
        if (CONCAT) {
            // permuted layout: words 0..63 = gcn (cp.async, 16B aligned),
            // words 64..65 = item_feat, words 66..67 = zero (pre-zeroed).
            const float4* G4 = reinterpret_cast<const float4*>(X2);
            for (int i = tid; i < TR * 16; i += THREADS) {
                int r = i >> 4, c4 = i & 15;
                int gr = row0 + r;
                uint32_t dst = smem_u32(Xb[0] + r * XS + 4 * c4);
                const float4* src = G4 + (size_t)(gr < M ? gr : 0) * 16 + c4;
                CP_ASYNC16(dst, src, (gr < M) ? 16 : 0);
            }
            CP_COMMIT();
            for (int r = tid; r < TR; r += THREADS) {
                int gr = row0 + r;
                float a0 = 0.f, a1 = 0.f;
                if (gr < M) { a0 = X1[gr * 2]; a1 = X1[gr * 2 + 1]; }
                Xb[0][r * XS + 64] = a0;
                Xb[0][r * XS + 65] = a1;
            }
        } else {
            for (int i = tid; i < TR * KV; i += THREADS) {
                int r = i / KV, c4 = i - r * KV;
                int gr = row0 + r;
                uint32_t dst = smem_u32(Xb[0] + r * XS + 4 * c4);
                const float4* src = X4 + (size_t)(gr < M ? gr : 0) * (K / 4) + c4;
                CP_ASYNC16(dst, src, (gr < M) ? 16 : 0);
            }
            CP_COMMIT();
        }

        u64 acc[R][C];
#pragma unroll
        for (int i = 0; i < R; ++i)
#pragma unroll
            for (int j = 0; j < C; ++j) acc[i][j] = 0ull;

#pragma unroll
        for (int cch = 0; cch < SPLIT; ++cch) {
            // prefetch next chunk into the other buffer
            if (SPLIT > 1 && cch + 1 < SPLIT) {
                const int nb = (cch + 1) & 1;
                for (int i = tid; i < TR * KV; i += THREADS) {
                    int r = i / KV, c4 = i - r * KV;
                    int gr = row0 + r;
                    uint32_t dst = smem_u32(Xb[nb] + r * XS + 4 * c4);
                    const float4* src = X4 + (size_t)(gr < M ? gr : 0) * (K / 4)
                                      + (cch + 1) * KV + c4;
                    CP_ASYNC16(dst, src, (gr < M) ? 16 : 0);
                }
                CP_COMMIT();
                cp_wait<1>();   // current chunk landed; next still in flight
            } else {
                cp_wait<0>();   // last (or only) chunk landed
            }
            __syncthreads();    // all threads' data visible

            const ulonglong2* xb = xbp[cch & 1];
            const int goff = cch * (KC / 4);
#pragma unroll 1
            for (int g = 0; g < NG; ++g) {
                ulonglong2 w[C];
#pragma unroll
                for (int j = 0; j < C; ++j) w[j] = wb[goff + g + j * WSTEP];
#pragma unroll
                for (int i = 0; i < R; ++i) {
                    ulonglong2 a = xb[g + i * XSTEP];   // warp-broadcast
#pragma unroll
                    for (int j = 0; j < C; ++j) {
                        FMA2(acc[i][j], a.x, w[j].x);
                        FMA2(acc[i][j], a.y, w[j].y);
                    }
                }
            }
            if (SPLIT > 1 && cch + 1 < SPLIT)
                __syncthreads();   // buf[cch&1] free before refill at cch+2
        }

        // ---- epilogue (registers + shfl only) ----
        float val[R][C];
#pragma unroll
        for (int i = 0; i < R; ++i)
#pragma unroll
            for (int j = 0; j < C; ++j) {
                float lo, hi;
                UNPACK2(lo, hi, acc[i][j]);
                val[i][j] = lo + hi + breg[j];
            }

        if (RELU) {
#pragma unroll
            for (int i = 0; i < R; ++i) {
                int gr = row0 + ty + G * i;
                if (gr < M) {
#pragma unroll
                    for (int j = 0; j < C; ++j)
                        Y[(size_t)gr * N + tx + LANES * j] = fmaxf(val[i][j], 0.f);
                }
            }
        } else {   // L2N: each row lives in one warp
#pragma unroll
            for (int i = 0; i < R; ++i) {
                float s = val[i][0] * val[i][0] + val[i][1] * val[i][1]
                        + val[i][2] * val[i][2] + val[i][3] * val[i][3];
#pragma unroll
                for (int o = 16; o > 0; o >>= 1)
                    s += __shfl_xor_sync(0xffffffffu, s, o);
                float scale = 1.0f / fmaxf(sqrtf(s), 1e-12f);
                int gr = row0 + ty + G * i;
                if (gr < M) {
#pragma unroll
                    for (int j = 0; j < C; ++j)
                        Y[(size_t)gr * 128 + tx + 32 * j] = val[i][j] * scale;
                }
            }
        }
    }
}

// ---------------------------------------------------------------------------
// Segment boundaries from sorted seg_ids (users with no interactions -> [0,0))
// ---------------------------------------------------------------------------
__global__ void bounds_init_kernel(int* __restrict__ s, int* __restrict__ e, int n)
{
    cudaTriggerProgrammaticLaunchCompletion();
    int i = blockIdx.x * blockDim.x + threadIdx.x;
    if (i < n) { s[i] = 0; e[i] = 0; }
}

__global__ void bounds_kernel(const int* __restrict__ seg, int n,
                              int* __restrict__ s, int* __restrict__ e)
{
    cudaTriggerProgrammaticLaunchCompletion();
    cudaGridDependencySynchronize();   // init's zeros must land first
    int i = blockIdx.x * blockDim.x + threadIdx.x;
    if (i >= n) return;
    int id = seg[i];
    if (i == 0 || seg[i - 1] != id) s[id] = i;
    if (i == n - 1 || seg[i + 1] != id) e[id] = i + 1;
}

// ---------------------------------------------------------------------------
// One warp per user: fused[u] = concat(gcn_user_emb[users[u]], mean(item_emb))
// PDL: the gue->fused copy reads only inputs and runs pre-sync (overlapping
// the l2-item tail); sa/ea/item_emb are consumed post-sync.
// ---------------------------------------------------------------------------
__global__ void hist_kernel(const float* __restrict__ item_emb,
                            const int* __restrict__ item_idx,
                            const int* __restrict__ sa,
                            const int* __restrict__ ea,
                            const float* __restrict__ gue,
                            const int* __restrict__ users,
                            float* __restrict__ fused, int n_users)
{
    cudaTriggerProgrammaticLaunchCompletion();
    int w = (blockIdx.x * blockDim.x + threadIdx.x) >> 5;
    int lane = threadIdx.x & 31;
    if (w >= n_users) return;

    int uu = users[w];

    if (lane < 16) {   // inputs only -> pre-sync
        float4 g = reinterpret_cast<const float4*>(gue + (size_t)uu * GCN)[lane];
        reinterpret_cast<float4*>(fused + (size_t)w * (GCN + TOW))[lane] = g;
    }

    cudaGridDependencySynchronize();   // item_emb + sa/ea valid from here

    int s = sa[uu], e = ea[uu];
    const float4* emb4 = reinterpret_cast<const float4*>(item_emb);

    float4 acc = make_float4(0.f, 0.f, 0.f, 0.f);
    int j = s;
    for (; j + 4 <= e; j += 4) {
        int i0 = item_idx[j], i1 = item_idx[j + 1], i2 = item_idx[j + 2], i3 = item_idx[j + 3];
        float4 v0 = emb4[(size_t)i0 * 32 + lane];
        float4 v1 = emb4[(size_t)i1 * 32 + lane];
        float4 v2 = emb4[(size_t)i2 * 32 + lane];
        float4 v3 = emb4[(size_t)i3 * 32 + lane];
        acc.x += (v0.x + v1.x) + (v2.x + v3.x);
        acc.y += (v0.y + v1.y) + (v2.y + v3.y);
        acc.z += (v0.z + v1.z) + (v2.z + v3.z);
        acc.w += (v0.w + v1.w) + (v2.w + v3.w);
    }
    for (; j < e; ++j) {
        int it = item_idx[j];
        float4 v = emb4[(size_t)it * 32 + lane];
        acc.x += v.x; acc.y += v.y; acc.z += v.z; acc.w += v.w;
    }
    float inv = 1.0f / fmaxf((float)(e - s), 1.0f);
    float4 m = make_float4(acc.x * inv, acc.y * inv, acc.z * inv, acc.w * inv);
    reinterpret_cast<float4*>(fused + (size_t)w * (GCN + TOW) + GCN)[lane] = m;
}

// ---------------------------------------------------------------------------
extern "C" void kernel_launch(void* const* d_in, const int* in_sizes, int n_in,
                              void* d_out, int out_size)
{
    const float* item_feat    = (const float*)d_in[0];
    const float* gcn_item_emb = (const float*)d_in[1];
    const float* gcn_user_emb = (const float*)d_in[2];
    const float* Wi1 = (const float*)d_in[3];
    const float* bi1 = (const float*)d_in[4];
    const float* Wi2 = (const float*)d_in[5];
    const float* bi2 = (const float*)d_in[6];
    const float* Wu1 = (const float*)d_in[7];
    const float* bu1 = (const float*)d_in[8];
    const float* Wu2 = (const float*)d_in[9];
    const float* bu2 = (const float*)d_in[10];
    const int* item_idx = (const int*)d_in[11];
    const int* seg_ids  = (const int*)d_in[12];
    const int* users    = (const int*)d_in[13];
    float* out = (float*)d_out;

    float *item_emb, *H, *fused;
    int *st, *en;
    cudaGetSymbolAddress((void**)&item_emb, g_item_emb);
    cudaGetSymbolAddress((void**)&H, g_H);
    cudaGetSymbolAddress((void**)&fused, g_fused);
    cudaGetSymbolAddress((void**)&st, g_start);
    cudaGetSymbolAddress((void**)&en, g_end);

    // instantiations (512 threads), per-layer R for tail/crossbar balance:
    //  i1: K=66  N=256 LANES=64 R=8 SPLIT=1 CONCAT  TR=64  (cp.async, permuted)
    //  l2: K=256 N=128 LANES=32 R=7 SPLIT=4 L2N     TR=112 (both towers, tail ~2%)
    //  u1: K=192 N=256 LANES=64 R=6 SPLIT=4 RELU    TR=48  (tail 2%)
    const int smem_i1 = (256 * PadK<66>::value  + 1 * 64  * PadK<66>::value) * 4; //  87,040
    const int smem_l2 = (128 * PadK<256>::value + 2 * 112 * 64) * 4;              // 190,464
    const int smem_u1 = (256 * PadK<192>::value + 2 * 48  * 48) * 4;              // 219,136

    cudaFuncSetAttribute((const void*)gemm_kernel<66, 256, 64, 8, 1, true, false, true>,
                         cudaFuncAttributeMaxDynamicSharedMemorySize, smem_i1);
    cudaFuncSetAttribute((const void*)gemm_kernel<256, 128, 32, 7, 4, false, true, false>,
                         cudaFuncAttributeMaxDynamicSharedMemorySize, smem_l2);
    cudaFuncSetAttribute((const void*)gemm_kernel<192, 256, 64, 6, 4, true, false, false>,
                         cudaFuncAttributeMaxDynamicSharedMemorySize, smem_u1);

    const int GRID = 152;   // persistent, 1 CTA per SM

    // PDL launch plumbing
    cudaLaunchAttribute pdl_attr[1];
    pdl_attr[0].id = cudaLaunchAttributeProgrammaticStreamSerialization;
    pdl_attr[0].val.programmaticStreamSerializationAllowed = 1;
    auto mkcfg = [&](unsigned gx, unsigned bx, size_t smem) {
        cudaLaunchConfig_t c;
        c.gridDim = dim3(gx, 1, 1);
        c.blockDim = dim3(bx, 1, 1);
        c.dynamicSmemBytes = smem;
        c.stream = 0;
        c.attrs = pdl_attr;
        c.numAttrs = 1;
        return c;
    };

    // 0) bounds init (first in chain; plain launch)
    bounds_init_kernel<<<(N_USERS + 255) / 256, 256>>>(st, en, N_USERS);

    // 1) bounds (syncs on init before writing)
    {
        cudaLaunchConfig_t c = mkcfg((N_INTER + 255) / 256, 256, 0);
        cudaLaunchKernelEx(&c, bounds_kernel, seg_ids, (int)N_INTER, st, en);
    }

    // 2) item L1: H = relu(concat @ Wi1 + bi1)   (permuted concat layout)
    {
        cudaLaunchConfig_t c = mkcfg(GRID, 512, smem_i1);
        cudaLaunchKernelEx(&c, gemm_kernel<66, 256, 64, 8, 1, true, false, true>,
                           item_feat, 2, gcn_item_emb, Wi1, bi1, H, (int)N_ITEMS);
    }

    // 3) item L2 + L2 norm -> item_emb
    {
        cudaLaunchConfig_t c = mkcfg(GRID, 512, smem_l2);
        cudaLaunchKernelEx(&c, gemm_kernel<256, 128, 32, 7, 4, false, true, false>,
                           (const float*)H, 256, (const float*)H, Wi2, bi2,
                           item_emb, (int)N_ITEMS);
    }

    // 4) ragged gather + mean -> fused (gue copy pre-sync, gather post-sync)
    {
        cudaLaunchConfig_t c = mkcfg((N_USERS * 32 + 255) / 256, 256, 0);
        cudaLaunchKernelEx(&c, hist_kernel,
                           (const float*)item_emb, item_idx,
                           (const int*)st, (const int*)en,
                           gcn_user_emb, users, fused, (int)N_USERS);
    }

    // 5) user L1
    {
        cudaLaunchConfig_t c = mkcfg(GRID, 512, smem_u1);
        cudaLaunchKernelEx(&c, gemm_kernel<192, 256, 64, 6, 4, true, false, false>,
                           (const float*)fused, 192, (const float*)fused, Wu1, bu1,
                           H, (int)N_USERS);
    }

    // 6) user L2 + L2 norm -> output
    {
        cudaLaunchConfig_t c = mkcfg(GRID, 512, smem_l2);
        cudaLaunchKernelEx(&c, gemm_kernel<256, 128, 32, 7, 4, false, true, false>,
                           (const float*)H, 256, (const float*)H, Wu2, bu2,
                           out, (int)N_USERS);
    }
}